// round 6
// baseline (speedup 1.0000x reference)
#include <cuda_runtime.h>
#include <math.h>

#define T_TOK 4096
#define DIM   768
#define NEXP  8
#define HID   2688
#define TOPK  2
#define NSLOT (T_TOK*TOPK)

#define BM 64
#define BN 64
#define BK 16

// ---------------- device scratch (allocation-free rule: __device__ globals) ---
__device__ int   g_cnt[NEXP];
__device__ int   g_list[NEXP * T_TOK];          // packed (token<<1)|k
__device__ float g_wts[NSLOT];                  // routing weight per (token,k) slot
__device__ float g_zsum;
__device__ float g_h[(size_t)NSLOT * HID];      // silu(x Wg) * (x Wu) per slot
__device__ float g_y[(size_t)NSLOT * DIM];      // per-slot down projection

// ---------------- init --------------------------------------------------------
__global__ void init_k() {
    if (threadIdx.x < NEXP) g_cnt[threadIdx.x] = 0;
    if (threadIdx.x == 0)   g_zsum = 0.f;
}

// ---------------- router: 1 warp per token ------------------------------------
__global__ __launch_bounds__(256) void router_k(const float* __restrict__ x,
                                                const float* __restrict__ gw,
                                                const float* __restrict__ eb) {
    int warp = (blockIdx.x * blockDim.x + threadIdx.x) >> 5;
    int lane = threadIdx.x & 31;
    if (warp >= T_TOK) return;
    const float* xr = x + (size_t)warp * DIM;

    float lg[NEXP];
#pragma unroll
    for (int e = 0; e < NEXP; e++) {
        const float* g = gw + e * DIM;
        float s = 0.f;
        for (int d = lane; d < DIM; d += 32) s += xr[d] * g[d];
#pragma unroll
        for (int o = 16; o; o >>= 1) s += __shfl_xor_sync(0xffffffffu, s, o);
        lg[e] = s;
    }
    if (lane == 0) {
        float bl[NEXP];
#pragma unroll
        for (int e = 0; e < NEXP; e++) bl[e] = lg[e] + eb[e];
        // top-2 on biased logits, first-index tie-break (strict >)
        int i0 = 0;
#pragma unroll
        for (int e = 1; e < NEXP; e++) if (bl[e] > bl[i0]) i0 = e;
        int i1 = -1;
#pragma unroll
        for (int e = 0; e < NEXP; e++) {
            if (e == i0) continue;
            if (i1 < 0 || bl[e] > bl[i1]) i1 = e;
        }
        // softmax over UNbiased logits at selected indices
        float l0 = lg[i0], l1 = lg[i1];
        float m  = fmaxf(l0, l1);
        float e0 = expf(l0 - m), e1 = expf(l1 - m);
        float inv = 1.f / (e0 + e1);
        g_wts[warp * 2 + 0] = e0 * inv;
        g_wts[warp * 2 + 1] = e1 * inv;
        int p0 = atomicAdd(&g_cnt[i0], 1); g_list[i0 * T_TOK + p0] = warp * 2 + 0;
        int p1 = atomicAdd(&g_cnt[i1], 1); g_list[i1 * T_TOK + p1] = warp * 2 + 1;
        // z-loss: logsumexp^2
        float mm = lg[0];
#pragma unroll
        for (int e = 1; e < NEXP; e++) mm = fmaxf(mm, lg[e]);
        float se = 0.f;
#pragma unroll
        for (int e = 0; e < NEXP; e++) se += expf(lg[e] - mm);
        float lse = mm + logf(se);
        atomicAdd(&g_zsum, lse * lse);
    }
}

// ---------------- gate+up grouped GEMM, silu fused, software-pipelined --------
// grid.x = NEXP*64 (expert, m-tile), grid.y = HID/BN
__global__ __launch_bounds__(256) void upgate_k(const float* __restrict__ x,
                                                const float* __restrict__ wg,
                                                const float* __restrict__ wu) {
    int e     = blockIdx.x >> 6;
    int mtile = blockIdx.x & 63;
    int cnt   = g_cnt[e];
    int m0    = mtile * BM;
    if (m0 >= cnt) return;
    int n0 = blockIdx.y * BN;

    __shared__ float As[BK][BM + 4];
    __shared__ float Bg[BK][BN];
    __shared__ float Bu[BK][BN];
    __shared__ int   slots[BM];

    int tid = threadIdx.x;
    if (tid < BM) {
        int r = m0 + tid;
        slots[tid] = (r < cnt) ? g_list[e * T_TOK + r] : -1;
    }
    __syncthreads();

    int arow = tid >> 2, ac4 = (tid & 3) * 4;
    int s    = slots[arow];
    const float* xrow = x + (size_t)((s >= 0) ? (s >> 1) : 0) * DIM;
    int brow = tid >> 4, bc = (tid & 15) * 4;
    const float* wgb = wg + (size_t)e * DIM * HID + n0;
    const float* wub = wu + (size_t)e * DIM * HID + n0;

    float aG[4][4] = {}, aU[4][4] = {};
    int tx = (tid & 15) * 4, ty = (tid >> 4) * 4;

    // prologue: fetch first tiles into registers
    float4 av  = *(const float4*)(xrow + ac4);
    float4 bgv = *(const float4*)(wgb + (size_t)brow * HID + bc);
    float4 buv = *(const float4*)(wub + (size_t)brow * HID + bc);

    for (int k0 = 0; k0 < DIM; k0 += BK) {
        As[ac4 + 0][arow] = av.x; As[ac4 + 1][arow] = av.y;
        As[ac4 + 2][arow] = av.z; As[ac4 + 3][arow] = av.w;
        *(float4*)&Bg[brow][bc] = bgv;
        *(float4*)&Bu[brow][bc] = buv;
        __syncthreads();

        int kn = k0 + BK;
        if (kn < DIM) {  // prefetch next tile (overlaps with FMA block below)
            av  = *(const float4*)(xrow + kn + ac4);
            bgv = *(const float4*)(wgb + (size_t)(kn + brow) * HID + bc);
            buv = *(const float4*)(wub + (size_t)(kn + brow) * HID + bc);
        }

#pragma unroll
        for (int kk = 0; kk < BK; kk++) {
            float4 ar = *(const float4*)&As[kk][ty];
            float4 bg = *(const float4*)&Bg[kk][tx];
            float4 bu = *(const float4*)&Bu[kk][tx];
            float arr[4] = {ar.x, ar.y, ar.z, ar.w};
            float bgr[4] = {bg.x, bg.y, bg.z, bg.w};
            float bur[4] = {bu.x, bu.y, bu.z, bu.w};
#pragma unroll
            for (int i = 0; i < 4; i++)
#pragma unroll
                for (int j = 0; j < 4; j++) {
                    aG[i][j] += arr[i] * bgr[j];
                    aU[i][j] += arr[i] * bur[j];
                }
        }
        __syncthreads();
    }

#pragma unroll
    for (int i = 0; i < 4; i++) {
        int sl = slots[ty + i];
        if (sl < 0) continue;
        float* hr = g_h + (size_t)sl * HID + n0 + tx;
        float4 o;
        {
            float g = aG[i][0]; float sg = g / (1.f + expf(-g)); o.x = sg * aU[i][0];
            g = aG[i][1]; sg = g / (1.f + expf(-g)); o.y = sg * aU[i][1];
            g = aG[i][2]; sg = g / (1.f + expf(-g)); o.z = sg * aU[i][2];
            g = aG[i][3]; sg = g / (1.f + expf(-g)); o.w = sg * aU[i][3];
        }
        *(float4*)hr = o;
    }
}

// ---------------- down grouped GEMM, software-pipelined -----------------------
// grid.x = NEXP*64, grid.y = DIM/BN
__global__ __launch_bounds__(256) void down_k(const float* __restrict__ wd) {
    int e     = blockIdx.x >> 6;
    int mtile = blockIdx.x & 63;
    int cnt   = g_cnt[e];
    int m0    = mtile * BM;
    if (m0 >= cnt) return;
    int n0 = blockIdx.y * BN;

    __shared__ float As[BK][BM + 4];
    __shared__ float Bt[BK][BN];
    __shared__ int   slots[BM];

    int tid = threadIdx.x;
    if (tid < BM) {
        int r = m0 + tid;
        slots[tid] = (r < cnt) ? g_list[e * T_TOK + r] : -1;
    }
    __syncthreads();

    int arow = tid >> 2, ac4 = (tid & 3) * 4;
    int s    = slots[arow];
    const float* hrow = g_h + (size_t)((s >= 0) ? s : 0) * HID;
    int brow = tid >> 4, bc = (tid & 15) * 4;
    const float* wdb = wd + (size_t)e * HID * DIM + n0;

    float acc[4][4] = {};
    int tx = (tid & 15) * 4, ty = (tid >> 4) * 4;

    float4 av = *(const float4*)(hrow + ac4);
    float4 bv = *(const float4*)(wdb + (size_t)brow * DIM + bc);

    for (int k0 = 0; k0 < HID; k0 += BK) {
        As[ac4 + 0][arow] = av.x; As[ac4 + 1][arow] = av.y;
        As[ac4 + 2][arow] = av.z; As[ac4 + 3][arow] = av.w;
        *(float4*)&Bt[brow][bc] = bv;
        __syncthreads();

        int kn = k0 + BK;
        if (kn < HID) {
            av = *(const float4*)(hrow + kn + ac4);
            bv = *(const float4*)(wdb + (size_t)(kn + brow) * DIM + bc);
        }

#pragma unroll
        for (int kk = 0; kk < BK; kk++) {
            float4 ar = *(const float4*)&As[kk][ty];
            float4 bb = *(const float4*)&Bt[kk][tx];
            float arr[4] = {ar.x, ar.y, ar.z, ar.w};
            float brr[4] = {bb.x, bb.y, bb.z, bb.w};
#pragma unroll
            for (int i = 0; i < 4; i++)
#pragma unroll
                for (int j = 0; j < 4; j++) acc[i][j] += arr[i] * brr[j];
        }
        __syncthreads();
    }

#pragma unroll
    for (int i = 0; i < 4; i++) {
        int sl = slots[ty + i];
        if (sl < 0) continue;
        float* yr = g_y + (size_t)sl * DIM + n0 + tx;
        float4 o = make_float4(acc[i][0], acc[i][1], acc[i][2], acc[i][3]);
        *(float4*)yr = o;
    }
}

// ---------------- combine with routing weights --------------------------------
__global__ void combine_k(float* __restrict__ out) {
    int i = blockIdx.x * blockDim.x + threadIdx.x;
    if (i >= T_TOK * DIM) return;
    int t = i / DIM, d = i - t * DIM;
    out[i] = g_wts[2 * t]     * g_y[(size_t)(2 * t)     * DIM + d]
           + g_wts[2 * t + 1] * g_y[(size_t)(2 * t + 1) * DIM + d];
}

__global__ void zloss_k(float* __restrict__ out, int pos) {
    out[pos] = 1e-5f * g_zsum / (float)T_TOK;
}

// ---------------- launch -------------------------------------------------------
extern "C" void kernel_launch(void* const* d_in, const int* in_sizes, int n_in,
                              void* d_out, int out_size) {
    const float* x     = (const float*)d_in[0];
    const float* gw    = (const float*)d_in[1];
    const float* eb    = (const float*)d_in[2];
    const float* wgate = (const float*)d_in[3];
    const float* wup   = (const float*)d_in[4];
    const float* wdown = (const float*)d_in[5];
    float* out = (float*)d_out;

    init_k<<<1, 32>>>();
    router_k<<<T_TOK / 8, 256>>>(x, gw, eb);

    dim3 g1(NEXP * 64, HID / BN);
    upgate_k<<<g1, 256>>>(x, wgate, wup);

    dim3 g2(NEXP * 64, DIM / BN);
    down_k<<<g2, 256>>>(wdown);

    combine_k<<<(T_TOK * DIM + 255) / 256, 256>>>(out);

    if (out_size > T_TOK * DIM)
        zloss_k<<<1, 1>>>(out, T_TOK * DIM);
}

// round 10
// speedup vs baseline: 1.0869x; 1.0869x over previous
#include <cuda_runtime.h>
#include <math.h>

#define T_TOK 4096
#define DIM   768
#define NEXP  8
#define HID   2688
#define TOPK  2
#define NSLOT (T_TOK*TOPK)

// ---------------- device scratch ----------------------------------------------
__device__ int   g_cnt[NEXP];
__device__ int   g_list[NEXP * T_TOK];
__device__ float g_wts[NSLOT];
__device__ float g_zsum;
__device__ float g_h[(size_t)NSLOT * HID];
__device__ float g_y[(size_t)NSLOT * DIM];

// ---------------- init --------------------------------------------------------
__global__ void init_k() {
    if (threadIdx.x < NEXP) g_cnt[threadIdx.x] = 0;
    if (threadIdx.x == 0)   g_zsum = 0.f;
}

// ---------------- router: 1 warp per token ------------------------------------
__global__ __launch_bounds__(256) void router_k(const float* __restrict__ x,
                                                const float* __restrict__ gw,
                                                const float* __restrict__ eb) {
    int warp = (blockIdx.x * blockDim.x + threadIdx.x) >> 5;
    int lane = threadIdx.x & 31;
    if (warp >= T_TOK) return;
    const float* xr = x + (size_t)warp * DIM;

    float lg[NEXP];
#pragma unroll
    for (int e = 0; e < NEXP; e++) {
        const float* g = gw + e * DIM;
        float s = 0.f;
        for (int d = lane; d < DIM; d += 32) s += xr[d] * g[d];
#pragma unroll
        for (int o = 16; o; o >>= 1) s += __shfl_xor_sync(0xffffffffu, s, o);
        lg[e] = s;
    }
    if (lane == 0) {
        float bl[NEXP];
#pragma unroll
        for (int e = 0; e < NEXP; e++) bl[e] = lg[e] + eb[e];
        int i0 = 0;
#pragma unroll
        for (int e = 1; e < NEXP; e++) if (bl[e] > bl[i0]) i0 = e;
        int i1 = -1;
#pragma unroll
        for (int e = 0; e < NEXP; e++) {
            if (e == i0) continue;
            if (i1 < 0 || bl[e] > bl[i1]) i1 = e;
        }
        float l0 = lg[i0], l1 = lg[i1];
        float m  = fmaxf(l0, l1);
        float e0 = expf(l0 - m), e1 = expf(l1 - m);
        float inv = 1.f / (e0 + e1);
        g_wts[warp * 2 + 0] = e0 * inv;
        g_wts[warp * 2 + 1] = e1 * inv;
        int p0 = atomicAdd(&g_cnt[i0], 1); g_list[i0 * T_TOK + p0] = warp * 2 + 0;
        int p1 = atomicAdd(&g_cnt[i1], 1); g_list[i1 * T_TOK + p1] = warp * 2 + 1;
        float mm = lg[0];
#pragma unroll
        for (int e = 1; e < NEXP; e++) mm = fmaxf(mm, lg[e]);
        float se = 0.f;
#pragma unroll
        for (int e = 0; e < NEXP; e++) se += expf(lg[e] - mm);
        float lse = mm + logf(se);
        atomicAdd(&g_zsum, lse * lse);
    }
}

// ---------------- gate+up grouped GEMM: 128x(64G+64U) tile, 8x8 microtile ------
// grid.x = NEXP*32 (expert, m-tile), grid.y = HID/64 = 42
__global__ __launch_bounds__(256) void upgate_k(const float* __restrict__ x,
                                                const float* __restrict__ wg,
                                                const float* __restrict__ wu) {
    int e     = blockIdx.x >> 5;
    int mtile = blockIdx.x & 31;
    int cnt   = g_cnt[e];
    int m0    = mtile * 128;
    if (m0 >= cnt) return;
    int n0 = blockIdx.y * 64;

    __shared__ float As[16][132];     // [k][row] 128 rows
    __shared__ float Bs[16][132];     // [k][col] cols 0-63 gate, 64-127 up
    __shared__ int   slots[128];

    int tid = threadIdx.x;
    if (tid < 128) {
        int r = m0 + tid;
        slots[tid] = (r < cnt) ? g_list[e * T_TOK + r] : -1;
    }
    __syncthreads();

    // A: each thread loads 2 float4 (rows ar0, ar0+64; cols ac..ac+3)
    int ar0 = tid >> 2, ar1 = ar0 + 64;
    int ac  = (tid & 3) * 4;
    int s0 = slots[ar0], s1 = slots[ar1];
    const float* xr0 = x + (size_t)((s0 >= 0) ? (s0 >> 1) : 0) * DIM;
    const float* xr1 = x + (size_t)((s1 >= 0) ? (s1 >> 1) : 0) * DIM;

    // B: each thread loads 2 float4 (k-rows br0, br0+8; same col group)
    int br0 = tid >> 5;               // 0..7
    int bc4 = tid & 31;               // 0..31 -> 0-15 gate, 16-31 up
    bool isup = bc4 >= 16;
    const float* wsrc = isup ? wu : wg;
    int bcol = n0 + (isup ? (bc4 - 16) * 4 : bc4 * 4);
    const float* bp = wsrc + (size_t)e * DIM * HID + bcol;
    int bs_off = bc4 * 4;

    int tx = tid & 15, ty = tid >> 4; // thread grid 16x16

    float acc[8][8];
#pragma unroll
    for (int i = 0; i < 8; i++)
#pragma unroll
        for (int j = 0; j < 8; j++) acc[i][j] = 0.f;

    float4 a0v = *(const float4*)(xr0 + ac);
    float4 a1v = *(const float4*)(xr1 + ac);
    float4 b0v = *(const float4*)(bp + (size_t)br0 * HID);
    float4 b1v = *(const float4*)(bp + (size_t)(br0 + 8) * HID);

    for (int k0 = 0; k0 < DIM; k0 += 16) {
        As[ac + 0][ar0] = a0v.x; As[ac + 1][ar0] = a0v.y;
        As[ac + 2][ar0] = a0v.z; As[ac + 3][ar0] = a0v.w;
        As[ac + 0][ar1] = a1v.x; As[ac + 1][ar1] = a1v.y;
        As[ac + 2][ar1] = a1v.z; As[ac + 3][ar1] = a1v.w;
        *(float4*)&Bs[br0][bs_off]     = b0v;
        *(float4*)&Bs[br0 + 8][bs_off] = b1v;
        __syncthreads();

        int kn = k0 + 16;
        if (kn < DIM) {
            a0v = *(const float4*)(xr0 + kn + ac);
            a1v = *(const float4*)(xr1 + kn + ac);
            b0v = *(const float4*)(bp + (size_t)(kn + br0) * HID);
            b1v = *(const float4*)(bp + (size_t)(kn + br0 + 8) * HID);
        }

#pragma unroll
        for (int kk = 0; kk < 16; kk++) {
            float4 af0 = *(const float4*)&As[kk][ty * 8];
            float4 af1 = *(const float4*)&As[kk][ty * 8 + 4];
            float4 bg  = *(const float4*)&Bs[kk][tx * 4];
            float4 bu  = *(const float4*)&Bs[kk][64 + tx * 4];
            float ar[8] = {af0.x, af0.y, af0.z, af0.w, af1.x, af1.y, af1.z, af1.w};
            float bgr[4] = {bg.x, bg.y, bg.z, bg.w};
            float bur[4] = {bu.x, bu.y, bu.z, bu.w};
#pragma unroll
            for (int i = 0; i < 8; i++) {
#pragma unroll
                for (int j = 0; j < 4; j++) {
                    acc[i][j]     += ar[i] * bgr[j];
                    acc[i][4 + j] += ar[i] * bur[j];
                }
            }
        }
        __syncthreads();
    }

#pragma unroll
    for (int i = 0; i < 8; i++) {
        int sl = slots[ty * 8 + i];
        if (sl < 0) continue;
        float4 o;
        float g;
        g = acc[i][0]; o.x = (g / (1.f + expf(-g))) * acc[i][4];
        g = acc[i][1]; o.y = (g / (1.f + expf(-g))) * acc[i][5];
        g = acc[i][2]; o.z = (g / (1.f + expf(-g))) * acc[i][6];
        g = acc[i][3]; o.w = (g / (1.f + expf(-g))) * acc[i][7];
        *(float4*)(g_h + (size_t)sl * HID + n0 + tx * 4) = o;
    }
}

// ---------------- down grouped GEMM: 128x128 tile, 8x8 microtile --------------
// grid.x = NEXP*32, grid.y = DIM/128 = 6
__global__ __launch_bounds__(256) void down_k(const float* __restrict__ wd) {
    int e     = blockIdx.x >> 5;
    int mtile = blockIdx.x & 31;
    int cnt   = g_cnt[e];
    int m0    = mtile * 128;
    if (m0 >= cnt) return;
    int n0 = blockIdx.y * 128;

    __shared__ float As[16][132];
    __shared__ float Bs[16][132];
    __shared__ int   slots[128];

    int tid = threadIdx.x;
    if (tid < 128) {
        int r = m0 + tid;
        slots[tid] = (r < cnt) ? g_list[e * T_TOK + r] : -1;
    }
    __syncthreads();

    int ar0 = tid >> 2, ar1 = ar0 + 64;
    int ac  = (tid & 3) * 4;
    int s0 = slots[ar0], s1 = slots[ar1];
    const float* hr0 = g_h + (size_t)((s0 >= 0) ? s0 : 0) * HID;
    const float* hr1 = g_h + (size_t)((s1 >= 0) ? s1 : 0) * HID;

    int br0 = tid >> 5;
    int bc4 = tid & 31;
    const float* bp = wd + (size_t)e * HID * DIM + n0 + bc4 * 4;
    int bs_off = bc4 * 4;

    int tx = tid & 15, ty = tid >> 4;

    float acc[8][8];
#pragma unroll
    for (int i = 0; i < 8; i++)
#pragma unroll
        for (int j = 0; j < 8; j++) acc[i][j] = 0.f;

    float4 a0v = *(const float4*)(hr0 + ac);
    float4 a1v = *(const float4*)(hr1 + ac);
    float4 b0v = *(const float4*)(bp + (size_t)br0 * DIM);
    float4 b1v = *(const float4*)(bp + (size_t)(br0 + 8) * DIM);

    for (int k0 = 0; k0 < HID; k0 += 16) {
        As[ac + 0][ar0] = a0v.x; As[ac + 1][ar0] = a0v.y;
        As[ac + 2][ar0] = a0v.z; As[ac + 3][ar0] = a0v.w;
        As[ac + 0][ar1] = a1v.x; As[ac + 1][ar1] = a1v.y;
        As[ac + 2][ar1] = a1v.z; As[ac + 3][ar1] = a1v.w;
        *(float4*)&Bs[br0][bs_off]     = b0v;
        *(float4*)&Bs[br0 + 8][bs_off] = b1v;
        __syncthreads();

        int kn = k0 + 16;
        if (kn < HID) {
            a0v = *(const float4*)(hr0 + kn + ac);
            a1v = *(const float4*)(hr1 + kn + ac);
            b0v = *(const float4*)(bp + (size_t)(kn + br0) * DIM);
            b1v = *(const float4*)(bp + (size_t)(kn + br0 + 8) * DIM);
        }

#pragma unroll
        for (int kk = 0; kk < 16; kk++) {
            float4 af0 = *(const float4*)&As[kk][ty * 8];
            float4 af1 = *(const float4*)&As[kk][ty * 8 + 4];
            float4 bf0 = *(const float4*)&Bs[kk][tx * 4];
            float4 bf1 = *(const float4*)&Bs[kk][64 + tx * 4];
            float ar[8] = {af0.x, af0.y, af0.z, af0.w, af1.x, af1.y, af1.z, af1.w};
            float br_[8] = {bf0.x, bf0.y, bf0.z, bf0.w, bf1.x, bf1.y, bf1.z, bf1.w};
#pragma unroll
            for (int i = 0; i < 8; i++)
#pragma unroll
                for (int j = 0; j < 8; j++) acc[i][j] += ar[i] * br_[j];
        }
        __syncthreads();
    }

#pragma unroll
    for (int i = 0; i < 8; i++) {
        int sl = slots[ty * 8 + i];
        if (sl < 0) continue;
        float* yr = g_y + (size_t)sl * DIM + n0;
        *(float4*)(yr + tx * 4)      = make_float4(acc[i][0], acc[i][1], acc[i][2], acc[i][3]);
        *(float4*)(yr + 64 + tx * 4) = make_float4(acc[i][4], acc[i][5], acc[i][6], acc[i][7]);
    }
}

// ---------------- combine with routing weights --------------------------------
__global__ void combine_k(float* __restrict__ out) {
    int i = blockIdx.x * blockDim.x + threadIdx.x;
    if (i >= T_TOK * DIM) return;
    int t = i / DIM, d = i - t * DIM;
    out[i] = g_wts[2 * t]     * g_y[(size_t)(2 * t)     * DIM + d]
           + g_wts[2 * t + 1] * g_y[(size_t)(2 * t + 1) * DIM + d];
}

__global__ void zloss_k(float* __restrict__ out, int pos) {
    out[pos] = 1e-5f * g_zsum / (float)T_TOK;
}

// ---------------- launch -------------------------------------------------------
extern "C" void kernel_launch(void* const* d_in, const int* in_sizes, int n_in,
                              void* d_out, int out_size) {
    const float* x     = (const float*)d_in[0];
    const float* gw    = (const float*)d_in[1];
    const float* eb    = (const float*)d_in[2];
    const float* wgate = (const float*)d_in[3];
    const float* wup   = (const float*)d_in[4];
    const float* wdown = (const float*)d_in[5];
    float* out = (float*)d_out;

    init_k<<<1, 32>>>();
    router_k<<<T_TOK / 8, 256>>>(x, gw, eb);

    dim3 g1(NEXP * 32, HID / 64);
    upgate_k<<<g1, 256>>>(x, wgate, wup);

    dim3 g2(NEXP * 32, DIM / 128);
    down_k<<<g2, 256>>>(wdown);

    combine_k<<<(T_TOK * DIM + 255) / 256, 256>>>(out);

    if (out_size > T_TOK * DIM)
        zloss_k<<<1, 1>>>(out, T_TOK * DIM);
}

// round 15
// speedup vs baseline: 1.1914x; 1.0962x over previous
#include <cuda_runtime.h>
#include <math.h>

#define T_TOK 4096
#define DIM   768
#define NEXP  8
#define HID   2688
#define TOPK  2
#define NSLOT (T_TOK*TOPK)

// ---------------- device scratch ----------------------------------------------
__device__ int   g_cnt[NEXP];
__device__ int   g_list[NEXP * T_TOK];
__device__ float g_wts[NSLOT];
__device__ float g_zsum;
__device__ float g_h[(size_t)NSLOT * HID];
__device__ float g_y[(size_t)NSLOT * DIM];

// ---------------- init --------------------------------------------------------
__global__ void init_k() {
    if (threadIdx.x < NEXP) g_cnt[threadIdx.x] = 0;
    if (threadIdx.x == 0)   g_zsum = 0.f;
}

// ---------------- router: 1 warp per token ------------------------------------
__global__ __launch_bounds__(256) void router_k(const float* __restrict__ x,
                                                const float* __restrict__ gw,
                                                const float* __restrict__ eb) {
    int warp = (blockIdx.x * blockDim.x + threadIdx.x) >> 5;
    int lane = threadIdx.x & 31;
    if (warp >= T_TOK) return;
    const float* xr = x + (size_t)warp * DIM;

    float lg[NEXP];
#pragma unroll
    for (int e = 0; e < NEXP; e++) {
        const float* g = gw + e * DIM;
        float s = 0.f;
        for (int d = lane; d < DIM; d += 32) s += xr[d] * g[d];
#pragma unroll
        for (int o = 16; o; o >>= 1) s += __shfl_xor_sync(0xffffffffu, s, o);
        lg[e] = s;
    }
    if (lane == 0) {
        float bl[NEXP];
#pragma unroll
        for (int e = 0; e < NEXP; e++) bl[e] = lg[e] + eb[e];
        int i0 = 0;
#pragma unroll
        for (int e = 1; e < NEXP; e++) if (bl[e] > bl[i0]) i0 = e;
        int i1 = -1;
#pragma unroll
        for (int e = 0; e < NEXP; e++) {
            if (e == i0) continue;
            if (i1 < 0 || bl[e] > bl[i1]) i1 = e;
        }
        float l0 = lg[i0], l1 = lg[i1];
        float m  = fmaxf(l0, l1);
        float e0 = expf(l0 - m), e1 = expf(l1 - m);
        float inv = 1.f / (e0 + e1);
        g_wts[warp * 2 + 0] = e0 * inv;
        g_wts[warp * 2 + 1] = e1 * inv;
        int p0 = atomicAdd(&g_cnt[i0], 1); g_list[i0 * T_TOK + p0] = warp * 2 + 0;
        int p1 = atomicAdd(&g_cnt[i1], 1); g_list[i1 * T_TOK + p1] = warp * 2 + 1;
        float mm = lg[0];
#pragma unroll
        for (int e = 1; e < NEXP; e++) mm = fmaxf(mm, lg[e]);
        float se = 0.f;
#pragma unroll
        for (int e = 0; e < NEXP; e++) se += expf(lg[e] - mm);
        float lse = mm + logf(se);
        atomicAdd(&g_zsum, lse * lse);
    }
}

// ---------------- gate+up grouped GEMM: 128x(64G+64U) tile, 8x8 microtile ------
// grid.x = NEXP*32 (expert, m-tile), grid.y = HID/64 = 42
// __launch_bounds__(256, 2): cap regs at 128/thread so 2 CTAs/SM co-reside and
// cross-CTA overlap hides the STS->BAR->LDS chain (occ was 12.5% @ 163 regs).
__global__ __launch_bounds__(256, 2) void upgate_k(const float* __restrict__ x,
                                                   const float* __restrict__ wg,
                                                   const float* __restrict__ wu) {
    int e     = blockIdx.x >> 5;
    int mtile = blockIdx.x & 31;
    int cnt   = g_cnt[e];
    int m0    = mtile * 128;
    if (m0 >= cnt) return;
    int n0 = blockIdx.y * 64;

    __shared__ float As[16][132];     // [k][row] 128 rows
    __shared__ float Bs[16][132];     // [k][col] cols 0-63 gate, 64-127 up
    __shared__ int   slots[128];

    int tid = threadIdx.x;
    if (tid < 128) {
        int r = m0 + tid;
        slots[tid] = (r < cnt) ? g_list[e * T_TOK + r] : -1;
    }
    __syncthreads();

    // A: each thread loads 2 float4 (rows ar0, ar0+64; cols ac..ac+3)
    int ar0 = tid >> 2, ar1 = ar0 + 64;
    int ac  = (tid & 3) * 4;
    int s0 = slots[ar0], s1 = slots[ar1];
    const float* xr0 = x + (size_t)((s0 >= 0) ? (s0 >> 1) : 0) * DIM;
    const float* xr1 = x + (size_t)((s1 >= 0) ? (s1 >> 1) : 0) * DIM;

    // B: each thread loads 2 float4 (k-rows br0, br0+8; same col group)
    int br0 = tid >> 5;               // 0..7
    int bc4 = tid & 31;               // 0..31 -> 0-15 gate, 16-31 up
    bool isup = bc4 >= 16;
    const float* wsrc = isup ? wu : wg;
    int bcol = n0 + (isup ? (bc4 - 16) * 4 : bc4 * 4);
    const float* bp = wsrc + (size_t)e * DIM * HID + bcol;
    int bs_off = bc4 * 4;

    int tx = tid & 15, ty = tid >> 4; // thread grid 16x16

    float acc[8][8];
#pragma unroll
    for (int i = 0; i < 8; i++)
#pragma unroll
        for (int j = 0; j < 8; j++) acc[i][j] = 0.f;

    float4 a0v = *(const float4*)(xr0 + ac);
    float4 a1v = *(const float4*)(xr1 + ac);
    float4 b0v = *(const float4*)(bp + (size_t)br0 * HID);
    float4 b1v = *(const float4*)(bp + (size_t)(br0 + 8) * HID);

    for (int k0 = 0; k0 < DIM; k0 += 16) {
        As[ac + 0][ar0] = a0v.x; As[ac + 1][ar0] = a0v.y;
        As[ac + 2][ar0] = a0v.z; As[ac + 3][ar0] = a0v.w;
        As[ac + 0][ar1] = a1v.x; As[ac + 1][ar1] = a1v.y;
        As[ac + 2][ar1] = a1v.z; As[ac + 3][ar1] = a1v.w;
        *(float4*)&Bs[br0][bs_off]     = b0v;
        *(float4*)&Bs[br0 + 8][bs_off] = b1v;
        __syncthreads();

        int kn = k0 + 16;
        if (kn < DIM) {
            a0v = *(const float4*)(xr0 + kn + ac);
            a1v = *(const float4*)(xr1 + kn + ac);
            b0v = *(const float4*)(bp + (size_t)(kn + br0) * HID);
            b1v = *(const float4*)(bp + (size_t)(kn + br0 + 8) * HID);
        }

#pragma unroll
        for (int kk = 0; kk < 16; kk++) {
            float4 af0 = *(const float4*)&As[kk][ty * 8];
            float4 af1 = *(const float4*)&As[kk][ty * 8 + 4];
            float4 bg  = *(const float4*)&Bs[kk][tx * 4];
            float4 bu  = *(const float4*)&Bs[kk][64 + tx * 4];
            float ar[8] = {af0.x, af0.y, af0.z, af0.w, af1.x, af1.y, af1.z, af1.w};
            float bgr[4] = {bg.x, bg.y, bg.z, bg.w};
            float bur[4] = {bu.x, bu.y, bu.z, bu.w};
#pragma unroll
            for (int i = 0; i < 8; i++) {
#pragma unroll
                for (int j = 0; j < 4; j++) {
                    acc[i][j]     += ar[i] * bgr[j];
                    acc[i][4 + j] += ar[i] * bur[j];
                }
            }
        }
        __syncthreads();
    }

#pragma unroll
    for (int i = 0; i < 8; i++) {
        int sl = slots[ty * 8 + i];
        if (sl < 0) continue;
        float4 o;
        float g;
        g = acc[i][0]; o.x = (g / (1.f + expf(-g))) * acc[i][4];
        g = acc[i][1]; o.y = (g / (1.f + expf(-g))) * acc[i][5];
        g = acc[i][2]; o.z = (g / (1.f + expf(-g))) * acc[i][6];
        g = acc[i][3]; o.w = (g / (1.f + expf(-g))) * acc[i][7];
        *(float4*)(g_h + (size_t)sl * HID + n0 + tx * 4) = o;
    }
}

// ---------------- down grouped GEMM: 128x128 tile, 8x8 microtile --------------
// grid.x = NEXP*32, grid.y = DIM/128 = 6
__global__ __launch_bounds__(256, 2) void down_k(const float* __restrict__ wd) {
    int e     = blockIdx.x >> 5;
    int mtile = blockIdx.x & 31;
    int cnt   = g_cnt[e];
    int m0    = mtile * 128;
    if (m0 >= cnt) return;
    int n0 = blockIdx.y * 128;

    __shared__ float As[16][132];
    __shared__ float Bs[16][132];
    __shared__ int   slots[128];

    int tid = threadIdx.x;
    if (tid < 128) {
        int r = m0 + tid;
        slots[tid] = (r < cnt) ? g_list[e * T_TOK + r] : -1;
    }
    __syncthreads();

    int ar0 = tid >> 2, ar1 = ar0 + 64;
    int ac  = (tid & 3) * 4;
    int s0 = slots[ar0], s1 = slots[ar1];
    const float* hr0 = g_h + (size_t)((s0 >= 0) ? s0 : 0) * HID;
    const float* hr1 = g_h + (size_t)((s1 >= 0) ? s1 : 0) * HID;

    int br0 = tid >> 5;
    int bc4 = tid & 31;
    const float* bp = wd + (size_t)e * HID * DIM + n0 + bc4 * 4;
    int bs_off = bc4 * 4;

    int tx = tid & 15, ty = tid >> 4;

    float acc[8][8];
#pragma unroll
    for (int i = 0; i < 8; i++)
#pragma unroll
        for (int j = 0; j < 8; j++) acc[i][j] = 0.f;

    float4 a0v = *(const float4*)(hr0 + ac);
    float4 a1v = *(const float4*)(hr1 + ac);
    float4 b0v = *(const float4*)(bp + (size_t)br0 * DIM);
    float4 b1v = *(const float4*)(bp + (size_t)(br0 + 8) * DIM);

    for (int k0 = 0; k0 < HID; k0 += 16) {
        As[ac + 0][ar0] = a0v.x; As[ac + 1][ar0] = a0v.y;
        As[ac + 2][ar0] = a0v.z; As[ac + 3][ar0] = a0v.w;
        As[ac + 0][ar1] = a1v.x; As[ac + 1][ar1] = a1v.y;
        As[ac + 2][ar1] = a1v.z; As[ac + 3][ar1] = a1v.w;
        *(float4*)&Bs[br0][bs_off]     = b0v;
        *(float4*)&Bs[br0 + 8][bs_off] = b1v;
        __syncthreads();

        int kn = k0 + 16;
        if (kn < HID) {
            a0v = *(const float4*)(hr0 + kn + ac);
            a1v = *(const float4*)(hr1 + kn + ac);
            b0v = *(const float4*)(bp + (size_t)(kn + br0) * DIM);
            b1v = *(const float4*)(bp + (size_t)(kn + br0 + 8) * DIM);
        }

#pragma unroll
        for (int kk = 0; kk < 16; kk++) {
            float4 af0 = *(const float4*)&As[kk][ty * 8];
            float4 af1 = *(const float4*)&As[kk][ty * 8 + 4];
            float4 bf0 = *(const float4*)&Bs[kk][tx * 4];
            float4 bf1 = *(const float4*)&Bs[kk][64 + tx * 4];
            float ar[8] = {af0.x, af0.y, af0.z, af0.w, af1.x, af1.y, af1.z, af1.w};
            float br_[8] = {bf0.x, bf0.y, bf0.z, bf0.w, bf1.x, bf1.y, bf1.z, bf1.w};
#pragma unroll
            for (int i = 0; i < 8; i++)
#pragma unroll
                for (int j = 0; j < 8; j++) acc[i][j] += ar[i] * br_[j];
        }
        __syncthreads();
    }

#pragma unroll
    for (int i = 0; i < 8; i++) {
        int sl = slots[ty * 8 + i];
        if (sl < 0) continue;
        float* yr = g_y + (size_t)sl * DIM + n0;
        *(float4*)(yr + tx * 4)      = make_float4(acc[i][0], acc[i][1], acc[i][2], acc[i][3]);
        *(float4*)(yr + 64 + tx * 4) = make_float4(acc[i][4], acc[i][5], acc[i][6], acc[i][7]);
    }
}

// ---------------- combine with routing weights --------------------------------
__global__ void combine_k(float* __restrict__ out) {
    int i = blockIdx.x * blockDim.x + threadIdx.x;
    if (i >= T_TOK * DIM) return;
    int t = i / DIM, d = i - t * DIM;
    out[i] = g_wts[2 * t]     * g_y[(size_t)(2 * t)     * DIM + d]
           + g_wts[2 * t + 1] * g_y[(size_t)(2 * t + 1) * DIM + d];
}

__global__ void zloss_k(float* __restrict__ out, int pos) {
    out[pos] = 1e-5f * g_zsum / (float)T_TOK;
}

// ---------------- launch -------------------------------------------------------
extern "C" void kernel_launch(void* const* d_in, const int* in_sizes, int n_in,
                              void* d_out, int out_size) {
    const float* x     = (const float*)d_in[0];
    const float* gw    = (const float*)d_in[1];
    const float* eb    = (const float*)d_in[2];
    const float* wgate = (const float*)d_in[3];
    const float* wup   = (const float*)d_in[4];
    const float* wdown = (const float*)d_in[5];
    float* out = (float*)d_out;

    init_k<<<1, 32>>>();
    router_k<<<T_TOK / 8, 256>>>(x, gw, eb);

    dim3 g1(NEXP * 32, HID / 64);
    upgate_k<<<g1, 256>>>(x, wgate, wup);

    dim3 g2(NEXP * 32, DIM / 128);
    down_k<<<g2, 256>>>(wdown);

    combine_k<<<(T_TOK * DIM + 255) / 256, 256>>>(out);

    if (out_size > T_TOK * DIM)
        zloss_k<<<1, 1>>>(out, T_TOK * DIM);
}